// round 10
// baseline (speedup 1.0000x reference)
#include <cuda_runtime.h>
#include <cuda_fp16.h>
#include <cstdint>

#define Bn 8
#define Hn 64
#define Wn 64
#define HW 4096
#define KK 9
#define EPSV 1e-4f
#define SAH 40   // wn_s row stride (halves): bank g*20+q distinct mod 32 -> conflict-free
#define SBH 40   // cols_s row stride (halves): same property

__device__ float g_xt[Bn * HW * 128];        // x transposed [b][hw][c], fp32
__device__ __half g_wnth[KK * 128 * 128];    // normalized wn [k][o][c], fp16

__device__ __forceinline__ uint32_t smem_u32(const void* p) {
    uint32_t a;
    asm("{ .reg .u64 t; cvta.to.shared.u64 t, %1; cvt.u32.u64 %0, t; }" : "=r"(a) : "l"(p));
    return a;
}
__device__ __forceinline__ void mma_f16(float* d, const uint32_t* a, const uint32_t* b) {
    asm volatile(
        "mma.sync.aligned.m16n8k16.row.col.f32.f16.f16.f32 "
        "{%0,%1,%2,%3}, {%4,%5,%6,%7}, {%8,%9}, {%0,%1,%2,%3};"
        : "+f"(d[0]), "+f"(d[1]), "+f"(d[2]), "+f"(d[3])
        : "r"(a[0]), "r"(a[1]), "r"(a[2]), "r"(a[3]), "r"(b[0]), "r"(b[1]));
}
#define CP_ASYNC16(dst, src) \
    asm volatile("cp.async.ca.shared.global [%0], [%1], 16;" :: "r"(dst), "l"(src) : "memory")
#define CP_COMMIT()  asm volatile("cp.async.commit_group;" ::: "memory")
#define CP_WAIT0()   asm volatile("cp.async.wait_group 0;" ::: "memory")

// bilinear gather parameters for one (pixel, k)
struct GP {
    const float *p00, *p01, *p10, *p11;
    float w00, w01, w10, w11;
};
__device__ __forceinline__ GP gparams(const float* __restrict__ xb,
                                      const float* __restrict__ offset,
                                      int b, int k, int gho, int gwo) {
    const int ky = k / 3, kx = k - ky * 3;
    const float offy = __ldg(&offset[(((b * 18) + 2 * k    ) * Hn + gho) * Wn + gwo]);
    const float offx = __ldg(&offset[(((b * 18) + 2 * k + 1) * Hn + gho) * Wn + gwo]);
    const float py  = (float)(gho - 1 + ky) + offy;
    const float pxf = (float)(gwo - 1 + kx) + offx;
    const float y0f = floorf(py), x0f = floorf(pxf);
    const float ly = py - y0f, lx = pxf - x0f;
    const int y0 = (int)y0f, x0 = (int)x0f, y1 = y0 + 1, x1 = x0 + 1;
    GP g;
    g.w00 = (1.f - ly) * (1.f - lx); g.w01 = (1.f - ly) * lx;
    g.w10 = ly * (1.f - lx);         g.w11 = ly * lx;
    if (!((y0 >= 0) & (y0 < Hn) & (x0 >= 0) & (x0 < Wn))) g.w00 = 0.f;
    if (!((y0 >= 0) & (y0 < Hn) & (x1 >= 0) & (x1 < Wn))) g.w01 = 0.f;
    if (!((y1 >= 0) & (y1 < Hn) & (x0 >= 0) & (x0 < Wn))) g.w10 = 0.f;
    if (!((y1 >= 0) & (y1 < Hn) & (x1 >= 0) & (x1 < Wn))) g.w11 = 0.f;
    const int yc0 = min(max(y0, 0), Hn - 1), yc1 = min(max(y1, 0), Hn - 1);
    const int xc0 = min(max(x0, 0), Wn - 1), xc1 = min(max(x1, 0), Wn - 1);
    g.p00 = xb + (size_t)(yc0 * Wn + xc0) * 128;
    g.p01 = xb + (size_t)(yc0 * Wn + xc1) * 128;
    g.p10 = xb + (size_t)(yc1 * Wn + xc0) * 128;
    g.p11 = xb + (size_t)(yc1 * Wn + xc1) * 128;
    return g;
}

// ---- kernel 1: prep = transpose x + normalize weights (fp16 out) ----
__global__ void prep_kernel(const float* __restrict__ x, const float* __restrict__ w) {
    if (blockIdx.x < 4096) {
        __shared__ float s[32][33];
        int id = blockIdx.x;
        int b = id >> 9, rest = id & 511;
        int c0 = (rest >> 7) * 32, hw0 = (rest & 127) * 32;
        int tx = threadIdx.x & 31, ty = threadIdx.x >> 5;
        #pragma unroll
        for (int p = 0; p < 4; p++)
            s[ty + p * 8][tx] = x[(size_t)(b * 128 + c0 + ty + p * 8) * HW + hw0 + tx];
        __syncthreads();
        #pragma unroll
        for (int p = 0; p < 4; p++)
            g_xt[(size_t)(b * HW + hw0 + ty + p * 8) * 128 + c0 + tx] = s[tx][ty + p * 8];
    } else {
        int k = blockIdx.x - 4096;
        int o = threadIdx.x;
        if (o < 128) {
            float s = 0.f;
            #pragma unroll 8
            for (int c = 0; c < 128; c++) { float v = w[(o * 128 + c) * KK + k]; s += v * v; }
            float inv = 1.0f / (sqrtf(s + 128.0f * EPSV) * 3.0f);
            #pragma unroll 8
            for (int c = 0; c < 128; c++)
                g_wnth[(size_t)(k * 128 + o) * 128 + c] =
                    __float2half_rn(w[(o * 128 + c) * KK + k] * inv);
        }
    }
}

// ---- kernel 2: main — pipelined im2col gather + fp16 mma.sync GEMM ----
// grid 256, 256 thr, 2 CTAs/SM. block = (b, 2 rows): D[128co][128px],
// 8 warps = 4m x 2n, each 32co x 64px. fp16 operands, fp32 accum.
__global__ __launch_bounds__(256, 2)
void deform_main_kernel(const float* __restrict__ offset, float* __restrict__ out) {
    __shared__ __half wn_s[2][128 * SAH];    // [stage][o][c]  10240 B/stage
    __shared__ __half col_s[2][128 * SBH];   // [stage][px][c] 10240 B/stage

    const int t = threadIdx.x;
    const int b = blockIdx.x >> 5;
    const int ho0 = (blockIdx.x & 31) * 2;

    // gather mapping: 2 threads per pixel (128 px), 16 channels each
    const int gpx = t >> 1, ht = t & 1;
    const int gho = ho0 + (gpx >> 6), gwo = gpx & 63;
    // mma mapping: 8 warps = 4m x 2n
    const int w = t >> 5, lane = t & 31;
    const int m0 = (w & 3) * 32, n0 = (w >> 2) * 64;
    const int g = lane >> 2, q = lane & 3;

    const uint32_t wnb_u32[2] = { smem_u32(&wn_s[0][0]), smem_u32(&wn_s[1][0]) };

    float acc[2][8][4];
    #pragma unroll
    for (int mt = 0; mt < 2; mt++)
        #pragma unroll
        for (int nt = 0; nt < 8; nt++)
            #pragma unroll
            for (int r = 0; r < 4; r++) acc[mt][nt][r] = 0.f;

    const float* xb = g_xt + (size_t)b * HW * 128;

    // ---- prologue: gather chunk 0 into col_s[0], cp.async wn chunk 0 ----
    GP gp = gparams(xb, offset, b, 0, gho, gwo);
    {
        #pragma unroll
        for (int sub = 0; sub < 4; sub++) {
            const int co = ht * 16 + sub * 4;
            float4 a = *(const float4*)(gp.p00 + co);
            float4 bb = *(const float4*)(gp.p01 + co);
            float4 c = *(const float4*)(gp.p10 + co);
            float4 d = *(const float4*)(gp.p11 + co);
            float v0 = gp.w00 * a.x + gp.w01 * bb.x + gp.w10 * c.x + gp.w11 * d.x;
            float v1 = gp.w00 * a.y + gp.w01 * bb.y + gp.w10 * c.y + gp.w11 * d.y;
            float v2 = gp.w00 * a.z + gp.w01 * bb.z + gp.w10 * c.z + gp.w11 * d.z;
            float v3 = gp.w00 * a.w + gp.w01 * bb.w + gp.w10 * c.w + gp.w11 * d.w;
            __half2 h0 = __floats2half2_rn(v0, v1);
            __half2 h1 = __floats2half2_rn(v2, v3);
            uint2 u = make_uint2(*(uint32_t*)&h0, *(uint32_t*)&h1);
            *(uint2*)&col_s[0][gpx * SBH + co] = u;
        }
        // wn chunk 0: 128 rows x 64B (32 halves), 512 granules of 16B
        const __half* srcb = g_wnth;   // k=0, cc=0
        #pragma unroll
        for (int p = 0; p < 2; p++) {
            int e = p * 256 + t;
            int row = e >> 2, off = e & 3;
            CP_ASYNC16(wnb_u32[0] + (uint32_t)(row * SAH + off * 8) * 2,
                       srcb + (size_t)row * 128 + off * 8);
        }
        CP_COMMIT();
        CP_WAIT0();
    }

    // ---- pipelined main loop over 36 chunks ----
    for (int it = 0; it < 36; it++) {
        const int cur = it & 1, nxt = cur ^ 1;
        __syncthreads();     // col_s[cur] visible; all warps done with [nxt]

        const bool more = (it + 1 < 36);
        if (more) {
            const int itn = it + 1;
            const __half* srcb = g_wnth + (size_t)(itn >> 2) * 128 * 128 + (itn & 3) * 32;
            #pragma unroll
            for (int p = 0; p < 2; p++) {
                int e = p * 256 + t;
                int row = e >> 2, off = e & 3;
                CP_ASYNC16(wnb_u32[nxt] + (uint32_t)(row * SAH + off * 8) * 2,
                           srcb + (size_t)row * 128 + off * 8);
            }
            CP_COMMIT();
            if (((it + 1) & 3) == 0)
                gp = gparams(xb, offset, b, (it + 1) >> 2, gho, gwo);
        }
        const int ccn = (it + 1) & 3;
        const __half* wnc = &wn_s[cur][0];
        const __half* colc = &col_s[cur][0];
        __half* coln = &col_s[nxt][0];

        uint32_t bf[8][2];
        #pragma unroll
        for (int j = 0; j < 4; j++) {
            const int ks = j >> 1, mth = j & 1;
            // issue next-chunk corner loads for this channel-quad
            float4 a, bb, c, d;
            if (more) {
                const int co = ccn * 32 + ht * 16 + j * 4;   // global channel in x_t
                a  = *(const float4*)(gp.p00 + co);
                bb = *(const float4*)(gp.p01 + co);
                c  = *(const float4*)(gp.p10 + co);
                d  = *(const float4*)(gp.p11 + co);
            }
            const int cb = ks * 16;      // k-base of this kstep within the 32-chunk
            if (mth == 0) {
                // load B fragments for this kstep (shared across both m-halves)
                #pragma unroll
                for (int nt = 0; nt < 8; nt++) {
                    const int px = n0 + nt * 8 + g;
                    bf[nt][0] = *(const uint32_t*)&colc[px * SBH + cb + 2 * q];
                    bf[nt][1] = *(const uint32_t*)&colc[px * SBH + cb + 2 * q + 8];
                }
            }
            // A fragment for m-half mth
            uint32_t af[4];
            {
                const int row = m0 + mth * 16 + g;
                af[0] = *(const uint32_t*)&wnc[(row    ) * SAH + cb + 2 * q];
                af[1] = *(const uint32_t*)&wnc[(row + 8) * SAH + cb + 2 * q];
                af[2] = *(const uint32_t*)&wnc[(row    ) * SAH + cb + 2 * q + 8];
                af[3] = *(const uint32_t*)&wnc[(row + 8) * SAH + cb + 2 * q + 8];
            }
            // 8 MMAs (mt = mth, nt = 0..7)
            #pragma unroll
            for (int nt = 0; nt < 8; nt++)
                mma_f16(acc[mth][nt], af, bf[nt]);

            // blend + STS.64 of next-chunk quad (local channels ht*16 + j*4)
            if (more) {
                float v0 = gp.w00 * a.x + gp.w01 * bb.x + gp.w10 * c.x + gp.w11 * d.x;
                float v1 = gp.w00 * a.y + gp.w01 * bb.y + gp.w10 * c.y + gp.w11 * d.y;
                float v2 = gp.w00 * a.z + gp.w01 * bb.z + gp.w10 * c.z + gp.w11 * d.z;
                float v3 = gp.w00 * a.w + gp.w01 * bb.w + gp.w10 * c.w + gp.w11 * d.w;
                __half2 h0 = __floats2half2_rn(v0, v1);
                __half2 h1 = __floats2half2_rn(v2, v3);
                uint2 u = make_uint2(*(uint32_t*)&h0, *(uint32_t*)&h1);
                *(uint2*)&coln[gpx * SBH + ht * 16 + j * 4] = u;
            }
        }
        if (more) CP_WAIT0();
    }

    // ---- epilogue: out[b][cout][ho][wo] ----
    const int ho = ho0 + (n0 >> 6);
    #pragma unroll
    for (int mt = 0; mt < 2; mt++) {
        const int r0 = m0 + mt * 16 + g;
        #pragma unroll
        for (int nt = 0; nt < 8; nt++) {
            const int wo = nt * 8 + 2 * q;
            float2 v0 = make_float2(acc[mt][nt][0], acc[mt][nt][1]);
            float2 v1 = make_float2(acc[mt][nt][2], acc[mt][nt][3]);
            *(float2*)&out[((size_t)(b * 128 + r0)     * HW) + ho * Wn + wo] = v0;
            *(float2*)&out[((size_t)(b * 128 + r0 + 8) * HW) + ho * Wn + wo] = v1;
        }
    }
}

// ---------------------------------------------------------------------------
extern "C" void kernel_launch(void* const* d_in, const int* in_sizes, int n_in,
                              void* d_out, int out_size) {
    const float* x      = (const float*)d_in[0];   // (8,128,64,64)
    const float* offset = (const float*)d_in[1];   // (8,18,64,64)
    const float* weight = (const float*)d_in[2];   // (128,128,3,3)
    float* out = (float*)d_out;                    // (8,128,64,64)

    prep_kernel<<<4105, 256>>>(x, weight);
    deform_main_kernel<<<256, 256>>>(offset, out);
}

// round 12
// speedup vs baseline: 1.1642x; 1.1642x over previous
#include <cuda_runtime.h>
#include <cuda_fp16.h>
#include <cstdint>

#define Bn 8
#define Hn 64
#define Wn 64
#define HW 4096
#define KK 9
#define EPSV 1e-4f
#define SAH 72   // smem row stride in halves (72 mod 32 = 8 words*2 -> conflict-free frags)

__device__ float  g_xt[Bn * HW * 128];              // x transposed [b][hw][c], fp32
__device__ __half g_wA[128 * 1152];                 // wn [o][k*128+c], fp16
__device__ __half g_cols[(size_t)KK * Bn * HW * 128];  // im2col [k][b*hw][c], fp16 (75.5MB)

__device__ __forceinline__ uint32_t smem_u32(const void* p) {
    uint32_t a;
    asm("{ .reg .u64 t; cvta.to.shared.u64 t, %1; cvt.u32.u64 %0, t; }" : "=r"(a) : "l"(p));
    return a;
}
__device__ __forceinline__ void mma_f16(float* d, const uint32_t* a, const uint32_t* b) {
    asm volatile(
        "mma.sync.aligned.m16n8k16.row.col.f32.f16.f16.f32 "
        "{%0,%1,%2,%3}, {%4,%5,%6,%7}, {%8,%9}, {%0,%1,%2,%3};"
        : "+f"(d[0]), "+f"(d[1]), "+f"(d[2]), "+f"(d[3])
        : "r"(a[0]), "r"(a[1]), "r"(a[2]), "r"(a[3]), "r"(b[0]), "r"(b[1]));
}
#define CP_ASYNC16(dst, src) \
    asm volatile("cp.async.ca.shared.global [%0], [%1], 16;" :: "r"(dst), "l"(src) : "memory")
#define CP_COMMIT()  asm volatile("cp.async.commit_group;" ::: "memory")
#define CP_WAIT0()   asm volatile("cp.async.wait_group 0;" ::: "memory")

// ---- kernel 1: prep = transpose x + normalize weights (coalesced fp16 out) ----
__global__ void prep_kernel(const float* __restrict__ x, const float* __restrict__ w) {
    if (blockIdx.x < 4096) {
        __shared__ float s[32][33];
        int id = blockIdx.x;
        int b = id >> 9, rest = id & 511;
        int c0 = (rest >> 7) * 32, hw0 = (rest & 127) * 32;
        int tx = threadIdx.x & 31, ty = threadIdx.x >> 5;
        #pragma unroll
        for (int p = 0; p < 4; p++)
            s[ty + p * 8][tx] = x[(size_t)(b * 128 + c0 + ty + p * 8) * HW + hw0 + tx];
        __syncthreads();
        #pragma unroll
        for (int p = 0; p < 4; p++)
            g_xt[(size_t)(b * HW + hw0 + ty + p * 8) * 128 + c0 + tx] = s[tx][ty + p * 8];
    } else {
        const int k = blockIdx.x - 4096;
        const int t = threadIdx.x;
        __shared__ float inv_s[128];
        if (t < 128) {                 // phase 1: thread = o, compute inv norm
            float s = 0.f;
            #pragma unroll 8
            for (int c = 0; c < 128; c++) { float v = w[(t * 128 + c) * KK + k]; s += v * v; }
            inv_s[t] = 1.0f / (sqrtf(s + 128.0f * EPSV) * 3.0f);
        }
        __syncthreads();
        if (t < 128) {                 // phase 2: thread = c, coalesced writes
            #pragma unroll 8
            for (int o = 0; o < 128; o++)
                g_wA[o * 1152 + k * 128 + t] =
                    __float2half_rn(w[(o * 128 + t) * KK + k] * inv_s[o]);
        }
    }
}

// ---- kernel 2: im2col — bilinear gather to g_cols[k][pxg][c], fp16 ----
// grid 512 = 8b x 64 rows; 256 thr; iter = k (9), 4 threads/pixel (32c each)
__global__ __launch_bounds__(256)
void im2col_kernel(const float* __restrict__ offset) {
    const int b   = blockIdx.x >> 6;
    const int row = blockIdx.x & 63;
    const int t   = threadIdx.x;
    const int px  = t >> 2;            // 0..63 (wo)
    const int h   = t & 3;             // channel quarter
    const int c0  = h * 32;
    const float* xb = g_xt + (size_t)b * HW * 128;
    const size_t pxg = (size_t)b * HW + row * Wn + px;

    for (int k = 0; k < KK; k++) {
        const int ky = k / 3, kx = k - ky * 3;
        const float offy = __ldg(&offset[(((b * 18) + 2 * k    ) * Hn + row) * Wn + px]);
        const float offx = __ldg(&offset[(((b * 18) + 2 * k + 1) * Hn + row) * Wn + px]);
        const float py  = (float)(row - 1 + ky) + offy;
        const float pxf = (float)(px  - 1 + kx) + offx;
        const float y0f = floorf(py), x0f = floorf(pxf);
        const float ly = py - y0f, lx = pxf - x0f;
        const int y0 = (int)y0f, x0 = (int)x0f, y1 = y0 + 1, x1 = x0 + 1;
        float w00 = (1.f - ly) * (1.f - lx), w01 = (1.f - ly) * lx;
        float w10 = ly * (1.f - lx),        w11 = ly * lx;
        if (!((y0 >= 0) & (y0 < Hn) & (x0 >= 0) & (x0 < Wn))) w00 = 0.f;
        if (!((y0 >= 0) & (y0 < Hn) & (x1 >= 0) & (x1 < Wn))) w01 = 0.f;
        if (!((y1 >= 0) & (y1 < Hn) & (x0 >= 0) & (x0 < Wn))) w10 = 0.f;
        if (!((y1 >= 0) & (y1 < Hn) & (x1 >= 0) & (x1 < Wn))) w11 = 0.f;
        const int yc0 = min(max(y0, 0), Hn - 1), yc1 = min(max(y1, 0), Hn - 1);
        const int xc0 = min(max(x0, 0), Wn - 1), xc1 = min(max(x1, 0), Wn - 1);
        const float* p00 = xb + (size_t)(yc0 * Wn + xc0) * 128 + c0;
        const float* p01 = xb + (size_t)(yc0 * Wn + xc1) * 128 + c0;
        const float* p10 = xb + (size_t)(yc1 * Wn + xc0) * 128 + c0;
        const float* p11 = xb + (size_t)(yc1 * Wn + xc1) * 128 + c0;

        uint32_t u[16];
        #pragma unroll
        for (int j = 0; j < 8; j++) {
            float4 a  = *(const float4*)(p00 + j * 4);
            float4 bb = *(const float4*)(p01 + j * 4);
            float4 c  = *(const float4*)(p10 + j * 4);
            float4 d  = *(const float4*)(p11 + j * 4);
            float v0 = w00 * a.x + w01 * bb.x + w10 * c.x + w11 * d.x;
            float v1 = w00 * a.y + w01 * bb.y + w10 * c.y + w11 * d.y;
            float v2 = w00 * a.z + w01 * bb.z + w10 * c.z + w11 * d.z;
            float v3 = w00 * a.w + w01 * bb.w + w10 * c.w + w11 * d.w;
            __half2 h0 = __floats2half2_rn(v0, v1);
            __half2 h1 = __floats2half2_rn(v2, v3);
            u[j * 2]     = *(uint32_t*)&h0;
            u[j * 2 + 1] = *(uint32_t*)&h1;
        }
        __half* dst = g_cols + ((size_t)k * (Bn * HW) + pxg) * 128 + c0;
        #pragma unroll
        for (int j = 0; j < 4; j++)
            *(uint4*)(dst + j * 8) = make_uint4(u[j*4], u[j*4+1], u[j*4+2], u[j*4+3]);
    }
}

// ---- kernel 3: dense fp16 GEMM — D[128o][128px] per CTA, K=1152 ----
// grid 256, 256 thr, 2 CTAs/SM, 18 chunks of K=64, double-buffered cp.async
__global__ __launch_bounds__(256, 2)
void gemm_kernel(float* __restrict__ out) {
    __shared__ __half wA_s[2][128 * SAH];   // [stage][o][kc]   18432 B/stage
    __shared__ __half wB_s[2][128 * SAH];   // [stage][px][kc]

    const int t = threadIdx.x;
    const int pxbase_g = blockIdx.x * 128;            // global pixel base
    const int b = pxbase_g >> 12;
    const int pxl0 = pxbase_g & (HW - 1);             // local pixel base in image

    const int w = t >> 5, lane = t & 31;
    const int m0 = (w & 3) * 32, n0 = (w >> 2) * 64;
    const int g = lane >> 2, q = lane & 3;

    const uint32_t wA_u32[2] = { smem_u32(&wA_s[0][0]), smem_u32(&wA_s[1][0]) };
    const uint32_t wB_u32[2] = { smem_u32(&wB_s[0][0]), smem_u32(&wB_s[1][0]) };

    float acc[2][8][4];
    #pragma unroll
    for (int mt = 0; mt < 2; mt++)
        #pragma unroll
        for (int nt = 0; nt < 8; nt++)
            #pragma unroll
            for (int r = 0; r < 4; r++) acc[mt][nt][r] = 0.f;

    // granule mapping: 4 per thread per operand: e = p*256+t, row=e>>3, off=e&7
    // prologue: chunk 0 -> stage 0
    {
        #pragma unroll
        for (int p = 0; p < 4; p++) {
            int e = p * 256 + t, row = e >> 3, off = e & 7;
            CP_ASYNC16(wA_u32[0] + (uint32_t)(row * SAH + off * 8) * 2,
                       g_wA + (size_t)row * 1152 + off * 8);
            CP_ASYNC16(wB_u32[0] + (uint32_t)(row * SAH + off * 8) * 2,
                       g_cols + ((size_t)0 * (Bn * HW) + pxbase_g + row) * 128 + off * 8);
        }
        CP_COMMIT();
        CP_WAIT0();
    }

    for (int it = 0; it < 18; it++) {
        const int cur = it & 1, nxt = cur ^ 1;
        __syncthreads();

        const bool more = (it + 1 < 18);
        if (more) {
            const int itn = it + 1;
            const int kt = itn >> 1, ch = (itn & 1) * 64;
            #pragma unroll
            for (int p = 0; p < 4; p++) {
                int e = p * 256 + t, row = e >> 3, off = e & 7;
                CP_ASYNC16(wA_u32[nxt] + (uint32_t)(row * SAH + off * 8) * 2,
                           g_wA + (size_t)row * 1152 + itn * 64 + off * 8);
                CP_ASYNC16(wB_u32[nxt] + (uint32_t)(row * SAH + off * 8) * 2,
                           g_cols + ((size_t)kt * (Bn * HW) + pxbase_g + row) * 128
                                  + ch + off * 8);
            }
            CP_COMMIT();
        }
        const __half* wAc = &wA_s[cur][0];
        const __half* wBc = &wB_s[cur][0];

        #pragma unroll
        for (int ks = 0; ks < 4; ks++) {
            const int cb = ks * 16;
            uint32_t bf[8][2];
            #pragma unroll
            for (int nt = 0; nt < 8; nt++) {
                const int px = n0 + nt * 8 + g;
                bf[nt][0] = *(const uint32_t*)&wBc[px * SAH + cb + 2 * q];
                bf[nt][1] = *(const uint32_t*)&wBc[px * SAH + cb + 2 * q + 8];
            }
            #pragma unroll
            for (int mt = 0; mt < 2; mt++) {
                const int row = m0 + mt * 16 + g;
                uint32_t af[4];
                af[0] = *(const uint32_t*)&wAc[(row    ) * SAH + cb + 2 * q];
                af[1] = *(const uint32_t*)&wAc[(row + 8) * SAH + cb + 2 * q];
                af[2] = *(const uint32_t*)&wAc[(row    ) * SAH + cb + 2 * q + 8];
                af[3] = *(const uint32_t*)&wAc[(row + 8) * SAH + cb + 2 * q + 8];
                #pragma unroll
                for (int nt = 0; nt < 8; nt++)
                    mma_f16(acc[mt][nt], af, bf[nt]);
            }
        }
        if (more) CP_WAIT0();
    }

    // epilogue: out[b][o][pxl]
    #pragma unroll
    for (int mt = 0; mt < 2; mt++) {
        const int r0 = m0 + mt * 16 + g;
        #pragma unroll
        for (int nt = 0; nt < 8; nt++) {
            const int pxl = pxl0 + n0 + nt * 8 + 2 * q;
            float2 v0 = make_float2(acc[mt][nt][0], acc[mt][nt][1]);
            float2 v1 = make_float2(acc[mt][nt][2], acc[mt][nt][3]);
            *(float2*)&out[((size_t)(b * 128 + r0)     * HW) + pxl] = v0;
            *(float2*)&out[((size_t)(b * 128 + r0 + 8) * HW) + pxl] = v1;
        }
    }
}

// ---------------------------------------------------------------------------
extern "C" void kernel_launch(void* const* d_in, const int* in_sizes, int n_in,
                              void* d_out, int out_size) {
    const float* x      = (const float*)d_in[0];   // (8,128,64,64)
    const float* offset = (const float*)d_in[1];   // (8,18,64,64)
    const float* weight = (const float*)d_in[2];   // (128,128,3,3)
    float* out = (float*)d_out;                    // (8,128,64,64)

    prep_kernel<<<4105, 256>>>(x, weight);
    im2col_kernel<<<512, 256>>>(offset);
    gemm_kernel<<<256, 256>>>(out);
}

// round 13
// speedup vs baseline: 2.1576x; 1.8533x over previous
#include <cuda_runtime.h>
#include <cstdint>

#define Bn 8
#define Hn 64
#define Wn 64
#define HW 4096
#define KK 9
#define EPSV 1e-4f
#define SA 136   // wn_s row stride (floats): conflict-free A-frag LDS
#define SB 36    // cols_s row stride (floats): conflict-free B-frag LDS

#define WN_FL   (32 * SA)                   // 4352 floats per wn stage
#define COL_FL  (128 * SB)                  // 4608 floats per cols stage
#define ST_FL   (128 * 8)                   // 1024 floats per state slot
#define SMEM_BYTES ((2 * (WN_FL + COL_FL) + 2 * ST_FL) * 4)   // 79872 B

__device__ float g_xt[Bn * HW * 128];       // x transposed [b][hw][c]
__device__ float g_wnt[KK * 128 * 128];     // normalized wn [k][c][o], tf32-rounded

__device__ __forceinline__ float to_tf32(float x) {
    float r; asm("cvt.rna.tf32.f32 %0, %1;" : "=f"(r) : "f"(x)); return r;
}
__device__ __forceinline__ uint32_t smem_u32(const void* p) {
    uint32_t a;
    asm("{ .reg .u64 t; cvta.to.shared.u64 t, %1; cvt.u32.u64 %0, t; }" : "=r"(a) : "l"(p));
    return a;
}
__device__ __forceinline__ void mma_tf32(float* d, const uint32_t* a, const uint32_t* b) {
    asm volatile(
        "mma.sync.aligned.m16n8k8.row.col.f32.tf32.tf32.f32 "
        "{%0,%1,%2,%3}, {%4,%5,%6,%7}, {%8,%9}, {%0,%1,%2,%3};"
        : "+f"(d[0]), "+f"(d[1]), "+f"(d[2]), "+f"(d[3])
        : "r"(a[0]), "r"(a[1]), "r"(a[2]), "r"(a[3]), "r"(b[0]), "r"(b[1]));
}
#define CP_ASYNC16(dst, src) \
    asm volatile("cp.async.ca.shared.global [%0], [%1], 16;" :: "r"(dst), "l"(src) : "memory")
#define CP_COMMIT()  asm volatile("cp.async.commit_group;" ::: "memory")
#define CP_WAIT0()   asm volatile("cp.async.wait_group 0;" ::: "memory")

// compute bilinear state for pixel px, tap k -> 8 floats {w00..w11, i00..i11}
__device__ __forceinline__ void write_state(float* stp, const float* __restrict__ offset,
                                            int b, int k, int px, int ho0) {
    const int gho = ho0 + (px >> 6), gwo = px & 63;
    const int ky = k / 3, kx = k - ky * 3;
    const float offy = __ldg(&offset[(((b * 18) + 2 * k    ) * Hn + gho) * Wn + gwo]);
    const float offx = __ldg(&offset[(((b * 18) + 2 * k + 1) * Hn + gho) * Wn + gwo]);
    const float py  = (float)(gho - 1 + ky) + offy;
    const float pxf = (float)(gwo - 1 + kx) + offx;
    const float y0f = floorf(py), x0f = floorf(pxf);
    const float ly = py - y0f, lx = pxf - x0f;
    const int y0 = (int)y0f, x0 = (int)x0f, y1 = y0 + 1, x1 = x0 + 1;
    float w00 = (1.f - ly) * (1.f - lx), w01 = (1.f - ly) * lx;
    float w10 = ly * (1.f - lx),        w11 = ly * lx;
    if (!((y0 >= 0) & (y0 < Hn) & (x0 >= 0) & (x0 < Wn))) w00 = 0.f;
    if (!((y0 >= 0) & (y0 < Hn) & (x1 >= 0) & (x1 < Wn))) w01 = 0.f;
    if (!((y1 >= 0) & (y1 < Hn) & (x0 >= 0) & (x0 < Wn))) w10 = 0.f;
    if (!((y1 >= 0) & (y1 < Hn) & (x1 >= 0) & (x1 < Wn))) w11 = 0.f;
    const int yc0 = min(max(y0, 0), Hn - 1), yc1 = min(max(y1, 0), Hn - 1);
    const int xc0 = min(max(x0, 0), Wn - 1), xc1 = min(max(x1, 0), Wn - 1);
    *(float4*)&stp[px * 8] = make_float4(w00, w01, w10, w11);
    *(float4*)&stp[px * 8 + 4] =
        make_float4(__int_as_float(yc0 * Wn + xc0), __int_as_float(yc0 * Wn + xc1),
                    __int_as_float(yc1 * Wn + xc0), __int_as_float(yc1 * Wn + xc1));
}

// ---- kernel 1: prep = transpose x (4096 blocks) + weights (36 blocks) ----
__global__ void prep_kernel(const float* __restrict__ x, const float* __restrict__ w) {
    if (blockIdx.x < 4096) {
        __shared__ float s[32][33];
        int id = blockIdx.x;
        int b = id >> 9, rest = id & 511;
        int c0 = (rest >> 7) * 32, hw0 = (rest & 127) * 32;
        int tx = threadIdx.x & 31, ty = threadIdx.x >> 5;
        #pragma unroll
        for (int p = 0; p < 4; p++)
            s[ty + p * 8][tx] = x[(size_t)(b * 128 + c0 + ty + p * 8) * HW + hw0 + tx];
        __syncthreads();
        #pragma unroll
        for (int p = 0; p < 4; p++)
            g_xt[(size_t)(b * HW + hw0 + ty + p * 8) * 128 + c0 + tx] = s[tx][ty + p * 8];
    } else {
        // weights: 36 blocks = 9k x 4 ogroups; 8 threads per o for the norm sum
        const int wb = blockIdx.x - 4096;
        const int k = wb >> 2, og = wb & 3;
        const int t = threadIdx.x;
        __shared__ float part[32][8];
        __shared__ float inv_s[32];
        {
            const int ol = t >> 3, sl = t & 7;     // o-local 0..31, slice 0..7
            const int o = og * 32 + ol;
            float s = 0.f;
            #pragma unroll
            for (int c = sl * 16; c < sl * 16 + 16; c++) {
                float v = w[(o * 128 + c) * KK + k]; s += v * v;
            }
            part[ol][sl] = s;
        }
        __syncthreads();
        if (t < 32) {
            float s = 0.f;
            #pragma unroll
            for (int j = 0; j < 8; j++) s += part[t][j];
            inv_s[t] = 1.0f / (sqrtf(s + 128.0f * EPSV) * 3.0f);
        }
        __syncthreads();
        // write 32 o x 128 c into g_wnt[k][c][o] (o-coalesced 128B segments)
        #pragma unroll
        for (int r = 0; r < 16; r++) {
            int e = r * 256 + t;
            int c = e >> 5, ol = e & 31;
            int o = og * 32 + ol;
            g_wnt[(k * 128 + c) * 128 + o] =
                to_tf32(w[(o * 128 + c) * KK + k] * inv_s[ol]);
        }
    }
}

// ---- kernel 2: main — pipelined gather (8 lanes/px) + tf32 mma.sync GEMM ----
// grid 256, 256 thr, 2 CTAs/SM. block = (b, 2 rows): D[128co][128px]
__global__ __launch_bounds__(256, 2)
void deform_main_kernel(const float* __restrict__ offset, float* __restrict__ out) {
    extern __shared__ float sm[];
    float* wnb[2]  = { sm, sm + WN_FL };
    float* colb[2] = { sm + 2 * WN_FL, sm + 2 * WN_FL + COL_FL };
    float* st      = sm + 2 * WN_FL + 2 * COL_FL;   // [2][128*8]
    const uint32_t wnb_u32[2] = { smem_u32(wnb[0]), smem_u32(wnb[1]) };

    const int t = threadIdx.x;
    const int b = blockIdx.x >> 5;
    const int ho0 = (blockIdx.x & 31) * 2;

    // gather mapping: 8 lanes/pixel, 4 passes of 32 px; lane covers 4 channels
    const int l8  = t & 7;             // lane within pixel
    const int pxq = t >> 3;            // 0..31: pixel = pass*32 + pxq
    // mma mapping: 8 warps = 4m x 2n
    const int w = t >> 5, lane = t & 31;
    const int m0 = (w & 3) * 32, n0 = (w >> 2) * 64;
    const int g = lane >> 2, q = lane & 3;

    float acc[2][8][4];
    #pragma unroll
    for (int mt = 0; mt < 2; mt++)
        #pragma unroll
        for (int nt = 0; nt < 8; nt++)
            #pragma unroll
            for (int r = 0; r < 4; r++) acc[mt][nt][r] = 0.f;

    const float* xb = g_xt + (size_t)b * HW * 128;

    // ---- prologue ----
    if (t < 128) write_state(st, offset, b, 0, t, ho0);   // k=0 -> slot 0
    {
        const float* src = g_wnt;   // wn chunk 0
        #pragma unroll
        for (int p = 0; p < 4; p++) {
            int e16 = p * 256 + t;
            int c = e16 >> 5, off = (e16 & 31) * 4;
            CP_ASYNC16(wnb_u32[0] + (uint32_t)(c * SA + off) * 4, src + e16 * 4);
        }
        CP_COMMIT();
    }
    __syncthreads();    // state(k0) visible
    #pragma unroll
    for (int p = 0; p < 4; p++) {    // gather chunk 0 into colb[0]
        const int px = p * 32 + pxq;
        float4 sw = *(const float4*)&st[px * 8];
        float4 si = *(const float4*)&st[px * 8 + 4];
        const float* base = xb + l8 * 4;
        float4 a  = *(const float4*)(base + (size_t)__float_as_int(si.x) * 128);
        float4 bb = *(const float4*)(base + (size_t)__float_as_int(si.y) * 128);
        float4 c  = *(const float4*)(base + (size_t)__float_as_int(si.z) * 128);
        float4 d  = *(const float4*)(base + (size_t)__float_as_int(si.w) * 128);
        float4 v;
        v.x = to_tf32(sw.x * a.x + sw.y * bb.x + sw.z * c.x + sw.w * d.x);
        v.y = to_tf32(sw.x * a.y + sw.y * bb.y + sw.z * c.y + sw.w * d.y);
        v.z = to_tf32(sw.x * a.z + sw.y * bb.z + sw.z * c.z + sw.w * d.z);
        v.w = to_tf32(sw.x * a.w + sw.y * bb.w + sw.z * c.w + sw.w * d.w);
        *(float4*)&colb[0][px * SB + l8 * 4] = v;
    }
    CP_WAIT0();

    // ---- pipelined main loop over 36 chunks ----
    for (int it = 0; it < 36; it++) {
        const int cur = it & 1, nxt = cur ^ 1;
        __syncthreads();

        const bool more = (it + 1 < 36);
        if (more) {
            const float* src = g_wnt + (size_t)(it + 1) * 4096;
            #pragma unroll
            for (int p = 0; p < 4; p++) {
                int e16 = p * 256 + t;
                int c = e16 >> 5, off = (e16 & 31) * 4;
                CP_ASYNC16(wnb_u32[nxt] + (uint32_t)(c * SA + off) * 4, src + e16 * 4);
            }
            CP_COMMIT();
        }
        // write state 2 chunks ahead (slot alternates with the one being read)
        if ((it + 2 < 36) && (((it + 2) & 3) == 0) && t < 128)
            write_state(st + (((it + 2) >> 2) & 1) * ST_FL, offset, b, (it + 2) >> 2, t, ho0);

        const float* stp = st + ((((it + 1) >> 2)) & 1) * ST_FL;
        const int ccn = (it + 1) & 3;
        const float* wnc = wnb[cur];
        const float* colc = colb[cur];
        float* coln = colb[nxt];

        #pragma unroll
        for (int sub = 0; sub < 4; sub++) {
            // issue next-chunk corner loads: pass `sub` (pixels sub*32..+31)
            float4 a, bb, c, d, swv;
            int px = 0;
            if (more) {
                px = sub * 32 + pxq;
                swv = *(const float4*)&stp[px * 8];
                float4 si = *(const float4*)&stp[px * 8 + 4];
                const float* base = xb + ccn * 32 + l8 * 4;
                a  = *(const float4*)(base + (size_t)__float_as_int(si.x) * 128);
                bb = *(const float4*)(base + (size_t)__float_as_int(si.y) * 128);
                c  = *(const float4*)(base + (size_t)__float_as_int(si.z) * 128);
                d  = *(const float4*)(base + (size_t)__float_as_int(si.w) * 128);
            }
            // MMA k-step (R8-verified fragment mappings)
            const int c8 = sub * 8;
            uint32_t af[2][4];
            #pragma unroll
            for (int mt = 0; mt < 2; mt++) {
                const int row = m0 + mt * 16 + g;
                af[mt][0] = __float_as_uint(wnc[(c8 + q) * SA + row]);
                af[mt][1] = __float_as_uint(wnc[(c8 + q) * SA + row + 8]);
                af[mt][2] = __float_as_uint(wnc[(c8 + q + 4) * SA + row]);
                af[mt][3] = __float_as_uint(wnc[(c8 + q + 4) * SA + row + 8]);
            }
            uint32_t bf[8][2];
            #pragma unroll
            for (int nt = 0; nt < 8; nt++) {
                const int bpx = n0 + nt * 8 + g;
                bf[nt][0] = __float_as_uint(colc[bpx * SB + c8 + q]);
                bf[nt][1] = __float_as_uint(colc[bpx * SB + c8 + q + 4]);
            }
            #pragma unroll
            for (int mt = 0; mt < 2; mt++)
                #pragma unroll
                for (int nt = 0; nt < 8; nt++)
                    mma_tf32(acc[mt][nt], af[mt], bf[nt]);

            // blend + STS.128 (one full 128B row per 8-lane pixel group)
            if (more) {
                float4 v;
                v.x = to_tf32(swv.x * a.x + swv.y * bb.x + swv.z * c.x + swv.w * d.x);
                v.y = to_tf32(swv.x * a.y + swv.y * bb.y + swv.z * c.y + swv.w * d.y);
                v.z = to_tf32(swv.x * a.z + swv.y * bb.z + swv.z * c.z + swv.w * d.z);
                v.w = to_tf32(swv.x * a.w + swv.y * bb.w + swv.z * c.w + swv.w * d.w);
                *(float4*)&coln[px * SB + l8 * 4] = v;
            }
        }
        if (more) CP_WAIT0();
    }

    // ---- epilogue: out[b][cout][ho][wo] ----
    const int ho = ho0 + (n0 >> 6);
    #pragma unroll
    for (int mt = 0; mt < 2; mt++) {
        const int r0 = m0 + mt * 16 + g;
        #pragma unroll
        for (int nt = 0; nt < 8; nt++) {
            const int wo = nt * 8 + 2 * q;
            float2 v0 = make_float2(acc[mt][nt][0], acc[mt][nt][1]);
            float2 v1 = make_float2(acc[mt][nt][2], acc[mt][nt][3]);
            *(float2*)&out[((size_t)(b * 128 + r0)     * HW) + ho * Wn + wo] = v0;
            *(float2*)&out[((size_t)(b * 128 + r0 + 8) * HW) + ho * Wn + wo] = v1;
        }
    }
}

// ---------------------------------------------------------------------------
extern "C" void kernel_launch(void* const* d_in, const int* in_sizes, int n_in,
                              void* d_out, int out_size) {
    const float* x      = (const float*)d_in[0];   // (8,128,64,64)
    const float* offset = (const float*)d_in[1];   // (8,18,64,64)
    const float* weight = (const float*)d_in[2];   // (128,128,3,3)
    float* out = (float*)d_out;                    // (8,128,64,64)

    cudaFuncSetAttribute(deform_main_kernel,
                         cudaFuncAttributeMaxDynamicSharedMemorySize, SMEM_BYTES);
    prep_kernel<<<4096 + 36, 256>>>(x, weight);
    deform_main_kernel<<<256, 256, SMEM_BYTES>>>(offset, out);
}